// round 2
// baseline (speedup 1.0000x reference)
#include <cuda_runtime.h>
#include <math.h>
#include <stdint.h>

// ---------------------------------------------------------------------------
// DiffractionIntegration — fp32, v2
//   nodeMLP (3 GEMMs + 2 LN/SiLU) -> structure factors (segment sums with
//   range-reduced sincos) -> diffraction net -> fusion net + residual.
// Tall GEMMs (M=200k) use a 128x64/BK16 8x4-microtile SGEMM; small B=256
// GEMMs use a 64x64 kernel. Scratch in __device__ globals. Capture-safe.
// ---------------------------------------------------------------------------

#define NNODE_MAX 200000
#define BMAX      256

__device__ float g_s1[(size_t)NNODE_MAX * 256];
__device__ float g_s2[(size_t)NNODE_MAX * 128];
__device__ float g_ff[(size_t)NNODE_MAX * 300];
__device__ float g_sf[BMAX * 600];
__device__ float g_d1[BMAX * 512];
__device__ float g_d2[BMAX * 256];
__device__ float g_d3[BMAX * 512];
__device__ float g_comb[BMAX * 1024];
__device__ float g_f1[BMAX * 512];
__device__ int   g_seg[BMAX + 1];

// ---------------------------------------------------------------------------
// Big SGEMM: C[M,N] = A[M,K] @ W[K,N] + bias[N]
// BM=128, BN=64, BK=16, 256 threads, 8x4 microtile. Requires K%16==0, N%4==0.
// ---------------------------------------------------------------------------
__global__ __launch_bounds__(256) void sgemm_big(
    const float* __restrict__ A, const float* __restrict__ W,
    const float* __restrict__ bias, float* __restrict__ C,
    int M, int N, int K)
{
    __shared__ float As[16][128];    // [k][m]
    __shared__ float Bs[16][68];     // [k][n] (+4 pad)

    const int t  = threadIdx.x;
    const int tx = t & 15;           // N dir: 4 cols each
    const int ty = t >> 4;           // M dir: 8 rows each
    const int n0 = blockIdx.x * 64;
    const int m0 = blockIdx.y * 128;

    float acc[8][4];
#pragma unroll
    for (int i = 0; i < 8; ++i)
#pragma unroll
        for (int j = 0; j < 4; ++j) acc[i][j] = 0.f;

    // A-load mapping: each thread loads 2 float4 of one row.
    const int a_row = t >> 1;            // 0..127
    const int a_c0  = (t & 1) * 8;       // 0 or 8
    // B-load mapping: 1 float4.
    const int b_row = t >> 4;            // 0..15
    const int b_c0  = (t & 15) * 4;      // 0..60

    const int kTiles = K >> 4;
    for (int kt = 0; kt < kTiles; ++kt) {
        const int k0 = kt << 4;
        // A tile [128 x 16] -> As[k][m]
        {
            const int gm = m0 + a_row;
            float4 v0 = make_float4(0.f,0.f,0.f,0.f);
            float4 v1 = make_float4(0.f,0.f,0.f,0.f);
            if (gm < M) {
                const float* p = &A[(size_t)gm * K + k0 + a_c0];
                v0 = *reinterpret_cast<const float4*>(p);
                v1 = *reinterpret_cast<const float4*>(p + 4);
            }
            As[a_c0 + 0][a_row] = v0.x; As[a_c0 + 1][a_row] = v0.y;
            As[a_c0 + 2][a_row] = v0.z; As[a_c0 + 3][a_row] = v0.w;
            As[a_c0 + 4][a_row] = v1.x; As[a_c0 + 5][a_row] = v1.y;
            As[a_c0 + 6][a_row] = v1.z; As[a_c0 + 7][a_row] = v1.w;
        }
        // B tile [16 x 64]
        {
            const int gn = n0 + b_c0;
            float4 v = make_float4(0.f,0.f,0.f,0.f);
            if (gn < N)   // N%4==0 -> whole float4 in range
                v = *reinterpret_cast<const float4*>(&W[(size_t)(k0 + b_row) * N + gn]);
            *reinterpret_cast<float4*>(&Bs[b_row][b_c0]) = v;
        }
        __syncthreads();

#pragma unroll
        for (int kk = 0; kk < 16; ++kk) {
            float4 a0 = *reinterpret_cast<const float4*>(&As[kk][ty * 8]);
            float4 a1 = *reinterpret_cast<const float4*>(&As[kk][ty * 8 + 4]);
            float4 bv = *reinterpret_cast<const float4*>(&Bs[kk][tx * 4]);
            float a[8] = {a0.x,a0.y,a0.z,a0.w,a1.x,a1.y,a1.z,a1.w};
            float b[4] = {bv.x,bv.y,bv.z,bv.w};
#pragma unroll
            for (int i = 0; i < 8; ++i)
#pragma unroll
                for (int j = 0; j < 4; ++j)
                    acc[i][j] = fmaf(a[i], b[j], acc[i][j]);
        }
        __syncthreads();
    }

#pragma unroll
    for (int i = 0; i < 8; ++i) {
        const int m = m0 + ty * 8 + i;
        if (m >= M) continue;
#pragma unroll
        for (int j = 0; j < 4; ++j) {
            const int n = n0 + tx * 4 + j;
            if (n >= N) continue;
            C[(size_t)m * N + n] = acc[i][j] + bias[n];
        }
    }
}

// ---------------------------------------------------------------------------
// Small SGEMM (B=256 rows): 64x64, BK=16, 4x4 microtile. K%4==0, N%4==0.
// ---------------------------------------------------------------------------
__global__ __launch_bounds__(256) void sgemm_small(
    const float* __restrict__ A, const float* __restrict__ W,
    const float* __restrict__ bias, const float* __restrict__ residual,
    float* __restrict__ C, int M, int N, int K)
{
    __shared__ float As[16][64];
    __shared__ float Bs[16][68];

    const int t  = threadIdx.x;
    const int tx = t & 15;
    const int ty = t >> 4;
    const int n0 = blockIdx.x * 64;
    const int m0 = blockIdx.y * 64;

    float acc[4][4];
#pragma unroll
    for (int i = 0; i < 4; ++i)
#pragma unroll
        for (int j = 0; j < 4; ++j) acc[i][j] = 0.f;

    const int kTiles = (K + 15) / 16;
    for (int kt = 0; kt < kTiles; ++kt) {
        const int k0 = kt * 16;
        {
            const int row = t >> 2;
            const int c4  = (t & 3) * 4;
            const int gm = m0 + row, gk = k0 + c4;
            float4 v = make_float4(0.f,0.f,0.f,0.f);
            if (gm < M && gk < K)   // K%4==0
                v = *reinterpret_cast<const float4*>(&A[(size_t)gm * K + gk]);
            As[c4 + 0][row] = v.x; As[c4 + 1][row] = v.y;
            As[c4 + 2][row] = v.z; As[c4 + 3][row] = v.w;
        }
        {
            const int rowk = t >> 4;
            const int c4   = (t & 15) * 4;
            const int gk = k0 + rowk, gn = n0 + c4;
            float4 v = make_float4(0.f,0.f,0.f,0.f);
            if (gk < K && gn < N)
                v = *reinterpret_cast<const float4*>(&W[(size_t)gk * N + gn]);
            *reinterpret_cast<float4*>(&Bs[rowk][c4]) = v;
        }
        __syncthreads();

#pragma unroll
        for (int kk = 0; kk < 16; ++kk) {
            float4 av = *reinterpret_cast<const float4*>(&As[kk][ty * 4]);
            float4 bv = *reinterpret_cast<const float4*>(&Bs[kk][tx * 4]);
            float a[4] = {av.x,av.y,av.z,av.w};
            float b[4] = {bv.x,bv.y,bv.z,bv.w};
#pragma unroll
            for (int i = 0; i < 4; ++i)
#pragma unroll
                for (int j = 0; j < 4; ++j)
                    acc[i][j] = fmaf(a[i], b[j], acc[i][j]);
        }
        __syncthreads();
    }

#pragma unroll
    for (int i = 0; i < 4; ++i) {
        const int m = m0 + ty * 4 + i;
        if (m >= M) continue;
#pragma unroll
        for (int j = 0; j < 4; ++j) {
            const int n = n0 + tx * 4 + j;
            if (n >= N) continue;
            float v = acc[i][j] + bias[n];
            if (residual) v += residual[(size_t)m * N + n];
            C[(size_t)m * N + n] = v;
        }
    }
}

// ---------------------------------------------------------------------------
// LayerNorm + SiLU. One block per row, blockDim == W.
// ---------------------------------------------------------------------------
__global__ void ln_silu_kernel(float* __restrict__ X, const float* __restrict__ g,
                               const float* __restrict__ b, int W, int do_silu)
{
    const int row = blockIdx.x;
    const int t = threadIdx.x;
    const int lane = t & 31, warp = t >> 5, nw = W >> 5;
    __shared__ float red[16];

    float x = X[(size_t)row * W + t];

    float s = x;
#pragma unroll
    for (int o = 16; o > 0; o >>= 1) s += __shfl_xor_sync(0xffffffffu, s, o);
    if (lane == 0) red[warp] = s;
    __syncthreads();
    float v = (lane < nw) ? red[lane] : 0.f;
#pragma unroll
    for (int o = 16; o > 0; o >>= 1) v += __shfl_xor_sync(0xffffffffu, v, o);
    const float mean = v / (float)W;
    __syncthreads();

    const float dx = x - mean;
    float s2 = dx * dx;
#pragma unroll
    for (int o = 16; o > 0; o >>= 1) s2 += __shfl_xor_sync(0xffffffffu, s2, o);
    if (lane == 0) red[warp] = s2;
    __syncthreads();
    float v2 = (lane < nw) ? red[lane] : 0.f;
#pragma unroll
    for (int o = 16; o > 0; o >>= 1) v2 += __shfl_xor_sync(0xffffffffu, v2, o);
    const float var = v2 / (float)W;

    float y = dx * rsqrtf(var + 1e-5f) * g[t] + b[t];
    if (do_silu) y = y * (1.0f / (1.0f + expf(-y)));
    X[(size_t)row * W + t] = y;
}

// ---------------------------------------------------------------------------
__global__ void seg_kernel(const int* __restrict__ batch, int N, int B)
{
    const int b = threadIdx.x + blockIdx.x * blockDim.x;
    if (b > B) return;
    int lo = 0, hi = N;
    while (lo < hi) {
        int mid = (lo + hi) >> 1;
        if (batch[mid] < b) lo = mid + 1; else hi = mid;
    }
    g_seg[b] = lo;
}

__global__ void zero_kernel(float* __restrict__ p, int n)
{
    int i = threadIdx.x + blockIdx.x * blockDim.x;
    if (i < n) p[i] = 0.f;
}

// ---------------------------------------------------------------------------
// Structure-factor accumulation. grid=(B, CHUNKS), 320 threads; thread j<300
// owns hkl j. Exact integer-period range reduction before __sincosf.
// ---------------------------------------------------------------------------
__global__ void accum_kernel(const float* __restrict__ ff,
                             const float* __restrict__ pos,
                             const float* __restrict__ hkl,
                             float* __restrict__ sf, int nchunks)
{
    const int b = blockIdx.x;
    const int chunk = blockIdx.y;
    const int j = threadIdx.x;
    if (j >= 300) return;

    const int s = g_seg[b], e = g_seg[b + 1];
    const int len = e - s;
    if (len <= 0) return;
    const int per = (len + nchunks - 1) / nchunks;
    const int n0 = s + chunk * per;
    const int n1 = (n0 + per < e) ? (n0 + per) : e;
    if (n0 >= e) return;

    const float hx = hkl[j * 3 + 0], hy = hkl[j * 3 + 1], hz = hkl[j * 3 + 2];
    float rj = 0.f, ij = 0.f;
    const float TWO_PI = 6.283185307179586f;

    for (int n = n0; n < n1; ++n) {
        const float px = __ldg(&pos[n * 3 + 0]);
        const float py = __ldg(&pos[n * 3 + 1]);
        const float pz = __ldg(&pos[n * 3 + 2]);
        const float f = ff[(size_t)n * 300 + j];
        float d = fmaf(px, hx, fmaf(py, hy, pz * hz));
        d -= rintf(d);
        float sn, cs;
        __sincosf(TWO_PI * d, &sn, &cs);
        rj = fmaf(f, cs, rj);
        ij = fmaf(f, sn, ij);
    }
    atomicAdd(&sf[b * 600 + 2 * j + 0], rj);
    atomicAdd(&sf[b * 600 + 2 * j + 1], ij);
}

// ---------------------------------------------------------------------------
__global__ void concat_kernel(const float* __restrict__ a,
                              const float* __restrict__ b,
                              float* __restrict__ out, int Wa, int Wb)
{
    const int row = blockIdx.x;
    for (int t = threadIdx.x; t < Wa + Wb; t += blockDim.x) {
        float v = (t < Wa) ? a[(size_t)row * Wa + t] : b[(size_t)row * Wb + (t - Wa)];
        out[(size_t)row * (Wa + Wb) + t] = v;
    }
}

// ---------------------------------------------------------------------------
extern "C" void kernel_launch(void* const* d_in, const int* in_sizes, int n_in,
                              void* d_out, int out_size)
{
    const float* graph  = (const float*)d_in[0];
    const float* nodef  = (const float*)d_in[1];
    const float* pos    = (const float*)d_in[2];
    const int*   batch  = (const int*)  d_in[3];
    const float* hkl    = (const float*)d_in[4];
    const float* ff_w1  = (const float*)d_in[5];
    const float* ff_b1  = (const float*)d_in[6];
    const float* ff_g1  = (const float*)d_in[7];
    const float* ff_bb1 = (const float*)d_in[8];
    const float* ff_w2  = (const float*)d_in[9];
    const float* ff_b2  = (const float*)d_in[10];
    const float* ff_g2  = (const float*)d_in[11];
    const float* ff_bb2 = (const float*)d_in[12];
    const float* ff_w3  = (const float*)d_in[13];
    const float* ff_b3  = (const float*)d_in[14];
    const float* dn_w1  = (const float*)d_in[15];
    const float* dn_b1  = (const float*)d_in[16];
    const float* dn_g1  = (const float*)d_in[17];
    const float* dn_bb1 = (const float*)d_in[18];
    const float* dn_w2  = (const float*)d_in[19];
    const float* dn_b2  = (const float*)d_in[20];
    const float* dn_g2  = (const float*)d_in[21];
    const float* dn_bb2 = (const float*)d_in[22];
    const float* dn_w3  = (const float*)d_in[23];
    const float* dn_b3  = (const float*)d_in[24];
    const float* fn_w1  = (const float*)d_in[25];
    const float* fn_b1  = (const float*)d_in[26];
    const float* fn_g   = (const float*)d_in[27];
    const float* fn_bb  = (const float*)d_in[28];
    const float* fn_w2  = (const float*)d_in[29];
    const float* fn_b2  = (const float*)d_in[30];
    float* out = (float*)d_out;

    const int N = in_sizes[3];
    const int B = in_sizes[0] / 512;

    float *s1, *s2, *ff, *sf, *dd1, *dd2, *dd3, *comb, *f1;
    cudaGetSymbolAddress((void**)&s1,   g_s1);
    cudaGetSymbolAddress((void**)&s2,   g_s2);
    cudaGetSymbolAddress((void**)&ff,   g_ff);
    cudaGetSymbolAddress((void**)&sf,   g_sf);
    cudaGetSymbolAddress((void**)&dd1,  g_d1);
    cudaGetSymbolAddress((void**)&dd2,  g_d2);
    cudaGetSymbolAddress((void**)&dd3,  g_d3);
    cudaGetSymbolAddress((void**)&comb, g_comb);
    cudaGetSymbolAddress((void**)&f1,   g_f1);

    auto gemm_big = [&](const float* A, const float* W, const float* bias,
                        float* C, int M, int Nc, int K) {
        dim3 grid((Nc + 63) / 64, (M + 127) / 128);
        sgemm_big<<<grid, 256>>>(A, W, bias, C, M, Nc, K);
    };
    auto gemm_small = [&](const float* A, const float* W, const float* bias,
                          const float* res, float* C, int M, int Nc, int K) {
        dim3 grid((Nc + 63) / 64, (M + 63) / 64);
        sgemm_small<<<grid, 256>>>(A, W, bias, res, C, M, Nc, K);
    };

    // --- node MLP ---
    gemm_big(nodef, ff_w1, ff_b1, s1, N, 256, 256);
    ln_silu_kernel<<<N, 256>>>(s1, ff_g1, ff_bb1, 256, 1);
    gemm_big(s1, ff_w2, ff_b2, s2, N, 128, 256);
    ln_silu_kernel<<<N, 128>>>(s2, ff_g2, ff_bb2, 128, 1);
    gemm_big(s2, ff_w3, ff_b3, ff, N, 300, 128);

    // --- structure factors ---
    seg_kernel<<<1, 512>>>(batch, N, B);
    zero_kernel<<<(B * 600 + 255) / 256, 256>>>(sf, B * 600);
    const int CHUNKS = 8;
    accum_kernel<<<dim3(B, CHUNKS), 320>>>(ff, pos, hkl, sf, CHUNKS);

    // --- diffraction net ---
    gemm_small(sf, dn_w1, dn_b1, nullptr, dd1, B, 512, 600);
    ln_silu_kernel<<<B, 512>>>(dd1, dn_g1, dn_bb1, 512, 1);
    gemm_small(dd1, dn_w2, dn_b2, nullptr, dd2, B, 256, 512);
    ln_silu_kernel<<<B, 256>>>(dd2, dn_g2, dn_bb2, 256, 1);
    gemm_small(dd2, dn_w3, dn_b3, nullptr, dd3, B, 512, 256);

    // --- fusion net + residual ---
    concat_kernel<<<B, 256>>>(graph, dd3, comb, 512, 512);
    gemm_small(comb, fn_w1, fn_b1, nullptr, f1, B, 512, 1024);
    ln_silu_kernel<<<B, 512>>>(f1, fn_g, fn_bb, 512, 1);
    gemm_small(f1, fn_w2, fn_b2, graph, out, B, 512, 512);
}

// round 4
// speedup vs baseline: 2.1238x; 2.1238x over previous
#include <cuda_runtime.h>
#include <math.h>
#include <stdint.h>

// ---------------------------------------------------------------------------
// DiffractionIntegration — v4 (= v3 + clamped predicated cp.async sources)
//   tf32 tensor-core GEMMs with fused LN+SiLU epilogues for tall layers;
//   fp32 small-batch chain; range-reduced sincos segment sums.
// ---------------------------------------------------------------------------

#define NNODE_MAX 200000
#define BMAX      256

__device__ float g_s1[(size_t)NNODE_MAX * 256];
__device__ float g_s2[(size_t)NNODE_MAX * 128];
__device__ float g_ff[(size_t)NNODE_MAX * 300];
__device__ float g_sf[BMAX * 600];
__device__ float g_d1[BMAX * 512];
__device__ float g_d2[BMAX * 256];
__device__ float g_d3[BMAX * 512];
__device__ float g_comb[BMAX * 1024];
__device__ float g_f1[BMAX * 512];
__device__ int   g_seg[BMAX + 1];

// ---------------------------------------------------------------------------
__device__ __forceinline__ void cp16(void* dst_smem, const void* src, int bytes)
{
    uint32_t d = (uint32_t)__cvta_generic_to_shared(dst_smem);
    asm volatile("cp.async.cg.shared.global [%0], [%1], 16, %2;"
                 :: "r"(d), "l"(src), "r"(bytes) : "memory");
}

// tf32 GEMM: C[M,N] = A[M,K] @ W[K,N] + bias, optional fused row LayerNorm+
// SiLU (requires BN == N, gridDim.x == 1). BM=64, BK=16, 256 threads,
// mma.sync.m16n8k8 tf32, fp32 accumulate, cp.async double buffering.
template<int BM, int BN, int WARPS_M, int WARPS_N, bool FUSE_LN, bool PRED_N>
__global__ __launch_bounds__(256, 2) void tf32_gemm(
    const float* __restrict__ A, const float* __restrict__ W,
    const float* __restrict__ bias, const float* __restrict__ gamma,
    const float* __restrict__ beta, float* __restrict__ C,
    int M, int N, int K)
{
    constexpr int BK   = 16;
    constexpr int WM   = BM / WARPS_M;
    constexpr int WN   = BN / WARPS_N;
    constexpr int MI   = WM / 16;
    constexpr int NI   = WN / 8;
    constexpr int ASTR = BK + 4;
    constexpr int BSTR = BN + 8;

    __shared__ __align__(16) float As[2][BM][ASTR];
    __shared__ __align__(16) float Bs[2][BK][BSTR];
    __shared__ float red[2][BM][WARPS_N];

    const int t    = threadIdx.x;
    const int lane = t & 31;
    const int warp = t >> 5;
    const int wm   = warp % WARPS_M;
    const int wn   = warp / WARPS_M;
    const int g    = lane >> 2;
    const int c    = lane & 3;
    const int m0   = blockIdx.y * BM;
    const int n0   = FUSE_LN ? 0 : blockIdx.x * BN;

    const int a_row = t >> 2;
    const int a_ch  = (t & 3) * 4;
    constexpr int B_CHUNKS = (BK * BN / 4) / 256;

    float acc[MI][NI][4];
#pragma unroll
    for (int mI = 0; mI < MI; ++mI)
#pragma unroll
        for (int nI = 0; nI < NI; ++nI)
#pragma unroll
            for (int r = 0; r < 4; ++r) acc[mI][nI][r] = 0.f;

    auto issue_tile = [&](int kt, int buf) {
        const int k0 = kt * BK;
        {
            const int gm = m0 + a_row;
            const bool ok = gm < M;
            const float* src = A + (ok ? ((size_t)gm * K + k0 + a_ch) : 0);
            cp16(&As[buf][a_row][a_ch], src, ok ? 16 : 0);
        }
#pragma unroll
        for (int i = 0; i < B_CHUNKS; ++i) {
            const int s  = t + i * 256;
            const int bk = s / (BN / 4);
            const int bn = (s % (BN / 4)) * 4;
            const bool ok = (!PRED_N || (n0 + bn) < N);
            const float* src = W + (ok ? ((size_t)(k0 + bk) * N + n0 + bn) : 0);
            cp16(&Bs[buf][bk][bn], src, ok ? 16 : 0);
        }
        asm volatile("cp.async.commit_group;" ::: "memory");
    };

    const int kTiles = K / BK;
    issue_tile(0, 0);

    for (int kt = 0; kt < kTiles; ++kt) {
        asm volatile("cp.async.wait_group 0;" ::: "memory");
        __syncthreads();
        if (kt + 1 < kTiles) issue_tile(kt + 1, (kt + 1) & 1);
        const int buf = kt & 1;
#pragma unroll
        for (int ks = 0; ks < 2; ++ks) {
            const int kb = ks * 8;
            uint32_t af[MI][4], bf[NI][2];
#pragma unroll
            for (int mI = 0; mI < MI; ++mI) {
                const int row = wm * WM + mI * 16;
                af[mI][0] = __float_as_uint(As[buf][row + g    ][kb + c    ]);
                af[mI][1] = __float_as_uint(As[buf][row + g + 8][kb + c    ]);
                af[mI][2] = __float_as_uint(As[buf][row + g    ][kb + c + 4]);
                af[mI][3] = __float_as_uint(As[buf][row + g + 8][kb + c + 4]);
            }
#pragma unroll
            for (int nI = 0; nI < NI; ++nI) {
                const int col = wn * WN + nI * 8 + g;
                bf[nI][0] = __float_as_uint(Bs[buf][kb + c    ][col]);
                bf[nI][1] = __float_as_uint(Bs[buf][kb + c + 4][col]);
            }
#pragma unroll
            for (int mI = 0; mI < MI; ++mI)
#pragma unroll
                for (int nI = 0; nI < NI; ++nI) {
                    float* d = acc[mI][nI];
                    asm volatile(
                        "mma.sync.aligned.m16n8k8.row.col.f32.tf32.tf32.f32 "
                        "{%0,%1,%2,%3}, {%4,%5,%6,%7}, {%8,%9}, {%0,%1,%2,%3};"
                        : "+f"(d[0]), "+f"(d[1]), "+f"(d[2]), "+f"(d[3])
                        : "r"(af[mI][0]), "r"(af[mI][1]),
                          "r"(af[mI][2]), "r"(af[mI][3]),
                          "r"(bf[nI][0]), "r"(bf[nI][1]));
                }
        }
    }

    // ---- bias ----
#pragma unroll
    for (int nI = 0; nI < NI; ++nI) {
        const int col = n0 + wn * WN + nI * 8 + 2 * c;
        float b0 = 0.f, b1 = 0.f;
        if (!PRED_N || col < N) { b0 = bias[col]; b1 = bias[col + 1]; }
#pragma unroll
        for (int mI = 0; mI < MI; ++mI) {
            acc[mI][nI][0] += b0; acc[mI][nI][1] += b1;
            acc[mI][nI][2] += b0; acc[mI][nI][3] += b1;
        }
    }

    float mean_[MI][2], rstd_[MI][2];
    if (FUSE_LN) {
#pragma unroll
        for (int mI = 0; mI < MI; ++mI)
#pragma unroll
            for (int h = 0; h < 2; ++h) {
                float s = 0.f, s2 = 0.f;
#pragma unroll
                for (int nI = 0; nI < NI; ++nI) {
                    const float v0 = acc[mI][nI][2 * h];
                    const float v1 = acc[mI][nI][2 * h + 1];
                    s += v0 + v1; s2 += v0 * v0 + v1 * v1;
                }
                s  += __shfl_xor_sync(0xffffffffu, s, 1);
                s  += __shfl_xor_sync(0xffffffffu, s, 2);
                s2 += __shfl_xor_sync(0xffffffffu, s2, 1);
                s2 += __shfl_xor_sync(0xffffffffu, s2, 2);
                if (c == 0) {
                    const int lr = wm * WM + mI * 16 + h * 8 + g;
                    red[0][lr][wn] = s;
                    red[1][lr][wn] = s2;
                }
            }
        __syncthreads();
#pragma unroll
        for (int mI = 0; mI < MI; ++mI)
#pragma unroll
            for (int h = 0; h < 2; ++h) {
                const int lr = wm * WM + mI * 16 + h * 8 + g;
                float s = 0.f, s2 = 0.f;
#pragma unroll
                for (int w = 0; w < WARPS_N; ++w) { s += red[0][lr][w]; s2 += red[1][lr][w]; }
                const float mean = s / (float)N;
                const float var  = s2 / (float)N - mean * mean;
                mean_[mI][h] = mean;
                rstd_[mI][h] = rsqrtf(var + 1e-5f);
            }
    }

    // ---- store ----
#pragma unroll
    for (int nI = 0; nI < NI; ++nI) {
        const int col = n0 + wn * WN + nI * 8 + 2 * c;
        if (PRED_N && col >= N) continue;
        float ga0 = 0.f, ga1 = 0.f, be0 = 0.f, be1 = 0.f;
        if (FUSE_LN) { ga0 = gamma[col]; ga1 = gamma[col + 1];
                       be0 = beta[col];  be1 = beta[col + 1]; }
#pragma unroll
        for (int mI = 0; mI < MI; ++mI)
#pragma unroll
            for (int h = 0; h < 2; ++h) {
                const int m = m0 + wm * WM + mI * 16 + h * 8 + g;
                if (m >= M) continue;
                float v0 = acc[mI][nI][2 * h];
                float v1 = acc[mI][nI][2 * h + 1];
                if (FUSE_LN) {
                    v0 = (v0 - mean_[mI][h]) * rstd_[mI][h] * ga0 + be0;
                    v1 = (v1 - mean_[mI][h]) * rstd_[mI][h] * ga1 + be1;
                    v0 = v0 / (1.f + __expf(-v0));
                    v1 = v1 / (1.f + __expf(-v1));
                }
                float2 o = make_float2(v0, v1);
                *reinterpret_cast<float2*>(&C[(size_t)m * N + col]) = o;
            }
    }
}

// ---------------------------------------------------------------------------
// Small SGEMM (B=256 rows): 64x64, BK=16, 4x4 microtile.
// ---------------------------------------------------------------------------
__global__ __launch_bounds__(256) void sgemm_small(
    const float* __restrict__ A, const float* __restrict__ W,
    const float* __restrict__ bias, const float* __restrict__ residual,
    float* __restrict__ C, int M, int N, int K)
{
    __shared__ float As[16][64];
    __shared__ float Bs[16][68];

    const int t  = threadIdx.x;
    const int tx = t & 15;
    const int ty = t >> 4;
    const int n0 = blockIdx.x * 64;
    const int m0 = blockIdx.y * 64;

    float acc[4][4];
#pragma unroll
    for (int i = 0; i < 4; ++i)
#pragma unroll
        for (int j = 0; j < 4; ++j) acc[i][j] = 0.f;

    const int kTiles = (K + 15) / 16;
    for (int kt = 0; kt < kTiles; ++kt) {
        const int k0 = kt * 16;
        {
            const int row = t >> 2;
            const int c4  = (t & 3) * 4;
            const int gm = m0 + row, gk = k0 + c4;
            float4 v = make_float4(0.f,0.f,0.f,0.f);
            if (gm < M && gk < K)
                v = *reinterpret_cast<const float4*>(&A[(size_t)gm * K + gk]);
            As[c4 + 0][row] = v.x; As[c4 + 1][row] = v.y;
            As[c4 + 2][row] = v.z; As[c4 + 3][row] = v.w;
        }
        {
            const int rowk = t >> 4;
            const int c4   = (t & 15) * 4;
            const int gk = k0 + rowk, gn = n0 + c4;
            float4 v = make_float4(0.f,0.f,0.f,0.f);
            if (gk < K && gn < N)
                v = *reinterpret_cast<const float4*>(&W[(size_t)gk * N + gn]);
            *reinterpret_cast<float4*>(&Bs[rowk][c4]) = v;
        }
        __syncthreads();

#pragma unroll
        for (int kk = 0; kk < 16; ++kk) {
            float4 av = *reinterpret_cast<const float4*>(&As[kk][ty * 4]);
            float4 bv = *reinterpret_cast<const float4*>(&Bs[kk][tx * 4]);
            float a[4] = {av.x,av.y,av.z,av.w};
            float b[4] = {bv.x,bv.y,bv.z,bv.w};
#pragma unroll
            for (int i = 0; i < 4; ++i)
#pragma unroll
                for (int j = 0; j < 4; ++j)
                    acc[i][j] = fmaf(a[i], b[j], acc[i][j]);
        }
        __syncthreads();
    }

#pragma unroll
    for (int i = 0; i < 4; ++i) {
        const int m = m0 + ty * 4 + i;
        if (m >= M) continue;
#pragma unroll
        for (int j = 0; j < 4; ++j) {
            const int n = n0 + tx * 4 + j;
            if (n >= N) continue;
            float v = acc[i][j] + bias[n];
            if (residual) v += residual[(size_t)m * N + n];
            C[(size_t)m * N + n] = v;
        }
    }
}

// ---------------------------------------------------------------------------
__global__ void ln_silu_kernel(float* __restrict__ X, const float* __restrict__ g,
                               const float* __restrict__ b, int W, int do_silu)
{
    const int row = blockIdx.x;
    const int t = threadIdx.x;
    const int lane = t & 31, warp = t >> 5, nw = W >> 5;
    __shared__ float red[16];

    float x = X[(size_t)row * W + t];

    float s = x;
#pragma unroll
    for (int o = 16; o > 0; o >>= 1) s += __shfl_xor_sync(0xffffffffu, s, o);
    if (lane == 0) red[warp] = s;
    __syncthreads();
    float v = (lane < nw) ? red[lane] : 0.f;
#pragma unroll
    for (int o = 16; o > 0; o >>= 1) v += __shfl_xor_sync(0xffffffffu, v, o);
    const float mean = v / (float)W;
    __syncthreads();

    const float dx = x - mean;
    float s2 = dx * dx;
#pragma unroll
    for (int o = 16; o > 0; o >>= 1) s2 += __shfl_xor_sync(0xffffffffu, s2, o);
    if (lane == 0) red[warp] = s2;
    __syncthreads();
    float v2 = (lane < nw) ? red[lane] : 0.f;
#pragma unroll
    for (int o = 16; o > 0; o >>= 1) v2 += __shfl_xor_sync(0xffffffffu, v2, o);
    const float var = v2 / (float)W;

    float y = dx * rsqrtf(var + 1e-5f) * g[t] + b[t];
    if (do_silu) y = y * (1.0f / (1.0f + expf(-y)));
    X[(size_t)row * W + t] = y;
}

// ---------------------------------------------------------------------------
__global__ void seg_kernel(const int* __restrict__ batch, int N, int B)
{
    const int b = threadIdx.x + blockIdx.x * blockDim.x;
    if (b > B) return;
    int lo = 0, hi = N;
    while (lo < hi) {
        int mid = (lo + hi) >> 1;
        if (batch[mid] < b) lo = mid + 1; else hi = mid;
    }
    g_seg[b] = lo;
}

__global__ void zero_kernel(float* __restrict__ p, int n)
{
    int i = threadIdx.x + blockIdx.x * blockDim.x;
    if (i < n) p[i] = 0.f;
}

// ---------------------------------------------------------------------------
__global__ void accum_kernel(const float* __restrict__ ff,
                             const float* __restrict__ pos,
                             const float* __restrict__ hkl,
                             float* __restrict__ sf, int nchunks)
{
    const int b = blockIdx.x;
    const int chunk = blockIdx.y;
    const int j = threadIdx.x;
    if (j >= 300) return;

    const int s = g_seg[b], e = g_seg[b + 1];
    const int len = e - s;
    if (len <= 0) return;
    const int per = (len + nchunks - 1) / nchunks;
    const int n0 = s + chunk * per;
    const int n1 = (n0 + per < e) ? (n0 + per) : e;
    if (n0 >= e) return;

    const float hx = hkl[j * 3 + 0], hy = hkl[j * 3 + 1], hz = hkl[j * 3 + 2];
    float rj = 0.f, ij = 0.f;
    const float TWO_PI = 6.283185307179586f;

    for (int n = n0; n < n1; ++n) {
        const float px = __ldg(&pos[n * 3 + 0]);
        const float py = __ldg(&pos[n * 3 + 1]);
        const float pz = __ldg(&pos[n * 3 + 2]);
        const float f = ff[(size_t)n * 300 + j];
        float d = fmaf(px, hx, fmaf(py, hy, pz * hz));
        d -= rintf(d);
        float sn, cs;
        __sincosf(TWO_PI * d, &sn, &cs);
        rj = fmaf(f, cs, rj);
        ij = fmaf(f, sn, ij);
    }
    atomicAdd(&sf[b * 600 + 2 * j + 0], rj);
    atomicAdd(&sf[b * 600 + 2 * j + 1], ij);
}

// ---------------------------------------------------------------------------
__global__ void concat_kernel(const float* __restrict__ a,
                              const float* __restrict__ b,
                              float* __restrict__ out, int Wa, int Wb)
{
    const int row = blockIdx.x;
    for (int t = threadIdx.x; t < Wa + Wb; t += blockDim.x) {
        float v = (t < Wa) ? a[(size_t)row * Wa + t] : b[(size_t)row * Wb + (t - Wa)];
        out[(size_t)row * (Wa + Wb) + t] = v;
    }
}

// ---------------------------------------------------------------------------
extern "C" void kernel_launch(void* const* d_in, const int* in_sizes, int n_in,
                              void* d_out, int out_size)
{
    const float* graph  = (const float*)d_in[0];
    const float* nodef  = (const float*)d_in[1];
    const float* pos    = (const float*)d_in[2];
    const int*   batch  = (const int*)  d_in[3];
    const float* hkl    = (const float*)d_in[4];
    const float* ff_w1  = (const float*)d_in[5];
    const float* ff_b1  = (const float*)d_in[6];
    const float* ff_g1  = (const float*)d_in[7];
    const float* ff_bb1 = (const float*)d_in[8];
    const float* ff_w2  = (const float*)d_in[9];
    const float* ff_b2  = (const float*)d_in[10];
    const float* ff_g2  = (const float*)d_in[11];
    const float* ff_bb2 = (const float*)d_in[12];
    const float* ff_w3  = (const float*)d_in[13];
    const float* ff_b3  = (const float*)d_in[14];
    const float* dn_w1  = (const float*)d_in[15];
    const float* dn_b1  = (const float*)d_in[16];
    const float* dn_g1  = (const float*)d_in[17];
    const float* dn_bb1 = (const float*)d_in[18];
    const float* dn_w2  = (const float*)d_in[19];
    const float* dn_b2  = (const float*)d_in[20];
    const float* dn_g2  = (const float*)d_in[21];
    const float* dn_bb2 = (const float*)d_in[22];
    const float* dn_w3  = (const float*)d_in[23];
    const float* dn_b3  = (const float*)d_in[24];
    const float* fn_w1  = (const float*)d_in[25];
    const float* fn_b1  = (const float*)d_in[26];
    const float* fn_g   = (const float*)d_in[27];
    const float* fn_bb  = (const float*)d_in[28];
    const float* fn_w2  = (const float*)d_in[29];
    const float* fn_b2  = (const float*)d_in[30];
    float* out = (float*)d_out;

    const int N = in_sizes[3];
    const int B = in_sizes[0] / 512;

    float *s1, *s2, *ff, *sf, *dd1, *dd2, *dd3, *comb, *f1;
    cudaGetSymbolAddress((void**)&s1,   g_s1);
    cudaGetSymbolAddress((void**)&s2,   g_s2);
    cudaGetSymbolAddress((void**)&ff,   g_ff);
    cudaGetSymbolAddress((void**)&sf,   g_sf);
    cudaGetSymbolAddress((void**)&dd1,  g_d1);
    cudaGetSymbolAddress((void**)&dd2,  g_d2);
    cudaGetSymbolAddress((void**)&dd3,  g_d3);
    cudaGetSymbolAddress((void**)&comb, g_comb);
    cudaGetSymbolAddress((void**)&f1,   g_f1);

    const int gy = (N + 63) / 64;

    // --- node MLP: tf32 tensor-core GEMMs, LN+SiLU fused for layers 1&2 ---
    tf32_gemm<64, 256, 2, 4, true,  false><<<dim3(1, gy), 256>>>(
        nodef, ff_w1, ff_b1, ff_g1, ff_bb1, s1, N, 256, 256);
    tf32_gemm<64, 128, 4, 2, true,  false><<<dim3(1, gy), 256>>>(
        s1, ff_w2, ff_b2, ff_g2, ff_bb2, s2, N, 128, 256);
    tf32_gemm<64, 64,  4, 2, false, true ><<<dim3(5, gy), 256>>>(
        s2, ff_w3, ff_b3, nullptr, nullptr, ff, N, 300, 128);

    // --- structure factors ---
    seg_kernel<<<1, 512>>>(batch, N, B);
    zero_kernel<<<(B * 600 + 255) / 256, 256>>>(sf, B * 600);
    const int CHUNKS = 8;
    accum_kernel<<<dim3(B, CHUNKS), 320>>>(ff, pos, hkl, sf, CHUNKS);

    // --- diffraction net (B rows) ---
    sgemm_small<<<dim3(8, (B + 63) / 64), 256>>>(sf, dn_w1, dn_b1, nullptr, dd1, B, 512, 600);
    ln_silu_kernel<<<B, 512>>>(dd1, dn_g1, dn_bb1, 512, 1);
    sgemm_small<<<dim3(4, (B + 63) / 64), 256>>>(dd1, dn_w2, dn_b2, nullptr, dd2, B, 256, 512);
    ln_silu_kernel<<<B, 256>>>(dd2, dn_g2, dn_bb2, 256, 1);
    sgemm_small<<<dim3(8, (B + 63) / 64), 256>>>(dd2, dn_w3, dn_b3, nullptr, dd3, B, 512, 256);

    // --- fusion net + residual ---
    concat_kernel<<<B, 256>>>(graph, dd3, comb, 512, 512);
    sgemm_small<<<dim3(8, (B + 63) / 64), 256>>>(comb, fn_w1, fn_b1, nullptr, f1, B, 512, 1024);
    ln_silu_kernel<<<B, 512>>>(f1, fn_g, fn_bb, 512, 1);
    sgemm_small<<<dim3(8, (B + 63) / 64), 256>>>(f1, fn_w2, fn_b2, graph, out, B, 512, 512);
}